// round 9
// baseline (speedup 1.0000x reference)
#include <cuda_runtime.h>

#define IN_SZ   448
#define OUT_SZ  224
#define BATCH   64
#define RPB     8
#define PLANE   (IN_SZ * IN_SZ)

// Per-(image, output index) coefficients (mask folded in)
__device__ float2 g_a[BATCH * OUT_SZ];   // col (a0, a1)
__device__ int2   g_c[BATCH * OUT_SZ];   // col (c0, c1)
__device__ float2 g_b[BATCH * OUT_SZ];   // row (b0, b1)
__device__ int2   g_r[BATCH * OUT_SZ];   // row (r0, r1)
__device__ int    g_cbase[BATCH];        // window col start, float4-aligned
__device__ int    g_chi[BATCH];          // window col end (inclusive)

__device__ __forceinline__ float sig10(float z) {
    return 1.0f / (1.0f + __expf(-10.0f * z));
}

// ---------------------------------------------------------------------------
// Prologue: coefficients. grid=64, block=224. Tiny.
// ---------------------------------------------------------------------------
__global__ void racnn_coef_kernel(const float* __restrict__ locs) {
    const int b = blockIdx.x;
    const int j = threadIdx.x;            // 0..223

    float tx = locs[b * 3 + 0];
    float ty = locs[b * 3 + 1];
    float tl = locs[b * 3 + 2];

    tl = fmaxf(tl, 448.0f / 3.0f);
    tx = fminf(fmaxf(tx, tl), 448.0f - tl);
    ty = fminf(fmaxf(ty, tl), 448.0f - tl);

    const float w_off = fmaxf(floorf(tx - tl), 0.0f);
    const float h_off = fmaxf(floorf(ty - tl), 0.0f);
    const float w_end = fminf(floorf(tx + tl), 448.0f);
    const float h_end = fminf(floorf(ty + tl), 448.0f);

    const float fj = (float)j;

    // row side (w axis)
    {
        const float step = (w_end - w_off - 1.0f) * (1.0f / 223.0f);
        const float src  = w_off + fj * step;
        const float r0f  = fminf(fmaxf(floorf(src), 0.0f), 447.0f);
        const float wr   = src - r0f;
        const int   r0   = (int)r0f;
        const int   r1   = min(r0 + 1, IN_SZ - 1);
        const float mr0  = sig10(r0f - w_off) - sig10(r0f - w_end);
        const float mr1  = sig10((float)r1 - w_off) - sig10((float)r1 - w_end);
        g_b[b * OUT_SZ + j] = make_float2((1.0f - wr) * mr0, wr * mr1);
        g_r[b * OUT_SZ + j] = make_int2(r0, r1);
    }

    // column side (h axis)
    {
        const float step = (h_end - h_off - 1.0f) * (1.0f / 223.0f);
        const float src  = h_off + fj * step;
        const float c0f  = fminf(fmaxf(floorf(src), 0.0f), 447.0f);
        const float wc   = src - c0f;
        const int   c0   = (int)c0f;
        const int   c1   = min(c0 + 1, IN_SZ - 1);
        const float mc0  = sig10(c0f - h_off) - sig10(c0f - h_end);
        const float mc1  = sig10((float)c1 - h_off) - sig10((float)c1 - h_end);
        g_a[b * OUT_SZ + j] = make_float2((1.0f - wc) * mc0, wc * mc1);
        g_c[b * OUT_SZ + j] = make_int2(c0, c1);

        if (j == 0)   g_cbase[b] = c0 & ~3;   // float4-aligned window start
        if (j == 223) g_chi[b]   = c1;        // max col (monotone in j)
    }
}

// ---------------------------------------------------------------------------
// Main: two-phase through smem.
// Block = (image b, channel ch, 8 output rows), 256 threads.
// Phase 1: warp k computes T[k][*] = b0*img[r0][*] + b1*img[r1][*] over the
//          crop window with float4 coalesced loads (8 independent LDG.128).
// Phase 2: 7 px/thread: 2 LDS + 1 FMA + coalesced STG.
// ---------------------------------------------------------------------------
__global__ __launch_bounds__(256) void racnn_smem_kernel(
    const float* __restrict__ img, float* __restrict__ out)
{
    __shared__ float T[RPB][IN_SZ];   // 14336 B, cbase-relative columns

    const int b       = blockIdx.z;
    const int ch      = blockIdx.y;
    const int jr_base = blockIdx.x * RPB;
    const int tid     = threadIdx.x;
    const int warp    = tid >> 5;
    const int lane    = tid & 31;

    const int cbase  = g_cbase[b];
    const int chi    = g_chi[b];
    // ceil(count/4), clamped so loads never cross column 447
    const int count4 = min((chi - cbase + 4) >> 2, (IN_SZ - cbase) >> 2);

    // ---- Phase 1: warp per T-row ----
    {
        const int2   r  = __ldg(&g_r[b * OUT_SZ + jr_base + warp]);
        const float2 bb = __ldg(&g_b[b * OUT_SZ + jr_base + warp]);

        const float4* p0 = (const float4*)(img + (size_t)(b * 3 + ch) * PLANE
                                               + r.x * IN_SZ + cbase);
        const float4* p1 = (const float4*)(img + (size_t)(b * 3 + ch) * PLANE
                                               + r.y * IN_SZ + cbase);

        float4 v0[4], v1[4];
        #pragma unroll
        for (int i = 0; i < 4; i++) {
            const int idx = lane + 32 * i;
            if (idx < count4) {
                v0[i] = __ldg(p0 + idx);
                v1[i] = __ldg(p1 + idx);
            }
        }
        #pragma unroll
        for (int i = 0; i < 4; i++) {
            const int idx = lane + 32 * i;
            if (idx < count4) {
                float4 t;
                t.x = fmaf(bb.y, v1[i].x, bb.x * v0[i].x);
                t.y = fmaf(bb.y, v1[i].y, bb.x * v0[i].y);
                t.z = fmaf(bb.y, v1[i].z, bb.x * v0[i].z);
                t.w = fmaf(bb.y, v1[i].w, bb.x * v0[i].w);
                *(float4*)&T[warp][idx << 2] = t;
            }
        }
    }
    __syncthreads();

    // ---- Phase 2: 7 px per thread ----
    float* obase = out + ((size_t)(b * 3 + ch) * OUT_SZ + jr_base) * OUT_SZ;

    #pragma unroll
    for (int i = 0; i < 7; i++) {
        const int p  = i * 256 + tid;            // 0..1791
        const int jr = p / OUT_SZ;
        const int jc = p - jr * OUT_SZ;
        const float2 a = __ldg(&g_a[b * OUT_SZ + jc]);
        const int2   c = __ldg(&g_c[b * OUT_SZ + jc]);
        const float t0 = T[jr][c.x - cbase];
        const float t1 = T[jr][c.y - cbase];
        obase[jr * OUT_SZ + jc] = fmaf(a.y, t1, a.x * t0);
    }
}

// ---------------------------------------------------------------------------
extern "C" void kernel_launch(void* const* d_in, const int* in_sizes, int n_in,
                              void* d_out, int out_size)
{
    const float* images = (const float*)d_in[0];
    const float* locs   = (const float*)d_in[1];
    if (n_in >= 2 && in_sizes[0] == BATCH * 3) {
        locs   = (const float*)d_in[0];
        images = (const float*)d_in[1];
    }
    float* out = (float*)d_out;

    racnn_coef_kernel<<<BATCH, OUT_SZ>>>(locs);

    dim3 block(256, 1, 1);
    dim3 grid(OUT_SZ / RPB, 3, BATCH);   // (28, 3, 64) = 5376 blocks
    racnn_smem_kernel<<<grid, block>>>(images, out);
}

// round 10
// speedup vs baseline: 1.0580x; 1.0580x over previous
#include <cuda_runtime.h>

#define IN_SZ   448
#define OUT_SZ  224
#define BATCH   64
#define PLANE   (IN_SZ * IN_SZ)

__device__ __forceinline__ float sig10(float z) {
    return 1.0f / (1.0f + __expf(-10.0f * z));
}

// Single kernel. Thread = 1 col x 2 rows x 3 channels = 6 px, 24 gather LDGs.
// Coefficients computed in registers per lane; sigmoid only near crop edges
// (|z| <= 1.5 band), elsewhere masks are exactly 1 -> a=(1-w, w).
// Block (32,8) = 256 threads = 32 cols x 16 rows tile; grid (7, 14, 64).
__global__ __launch_bounds__(256) void racnn_kernel(
    const float* __restrict__ img, const float* __restrict__ locs,
    float* __restrict__ out)
{
    const int b  = blockIdx.z;
    const int jc = blockIdx.x * 32 + threadIdx.x;          // 0..223
    const int jr = blockIdx.y * 16 + threadIdx.y * 2;      // first of 2 rows

    // ---- crop params (uniform per image; ~10 flops) ----
    float tx = __ldg(&locs[b * 3 + 0]);
    float ty = __ldg(&locs[b * 3 + 1]);
    float tl = __ldg(&locs[b * 3 + 2]);

    tl = fmaxf(tl, 448.0f / 3.0f);
    tx = fminf(fmaxf(tx, tl), 448.0f - tl);
    ty = fminf(fmaxf(ty, tl), 448.0f - tl);

    const float w_off = fmaxf(floorf(tx - tl), 0.0f);
    const float h_off = fmaxf(floorf(ty - tl), 0.0f);
    const float w_end = fminf(floorf(tx + tl), 448.0f);
    const float h_end = fminf(floorf(ty + tl), 448.0f);

    // ---- column coefficients (per lane) ----
    const float step_c = (h_end - h_off - 1.0f) * (1.0f / 223.0f);
    const float src_c  = h_off + (float)jc * step_c;
    const float c0f    = fminf(fmaxf(floorf(src_c), 0.0f), 447.0f);
    const float wc     = src_c - c0f;
    const int   c0     = (int)c0f;
    const int   c1     = min(c0 + 1, IN_SZ - 1);

    float a0, a1;
    if (c0f - h_off > 1.5f && c0f - h_end < -2.5f) {
        a0 = 1.0f - wc;  a1 = wc;            // interior: mask == 1
    } else {
        const float mc0 = sig10(c0f - h_off) - sig10(c0f - h_end);
        const float c1f = (float)c1;
        const float mc1 = sig10(c1f - h_off) - sig10(c1f - h_end);
        a0 = (1.0f - wc) * mc0;  a1 = wc * mc1;
    }

    // ---- row coefficients for 2 rows (warp-uniform branch) ----
    const float step_r = (w_end - w_off - 1.0f) * (1.0f / 223.0f);
    int   r0[2], r1[2];
    float b0[2], b1[2];
    #pragma unroll
    for (int k = 0; k < 2; k++) {
        const float src = w_off + (float)(jr + k) * step_r;
        const float r0f = fminf(fmaxf(floorf(src), 0.0f), 447.0f);
        const float wr  = src - r0f;
        r0[k] = (int)r0f;
        r1[k] = min(r0[k] + 1, IN_SZ - 1);
        if (r0f - w_off > 1.5f && r0f - w_end < -2.5f) {
            b0[k] = 1.0f - wr;  b1[k] = wr;
        } else {
            const float mr0 = sig10(r0f - w_off) - sig10(r0f - w_end);
            const float r1f = (float)r1[k];
            const float mr1 = sig10(r1f - w_off) - sig10(r1f - w_end);
            b0[k] = (1.0f - wr) * mr0;  b1[k] = wr * mr1;
        }
    }

    // ---- gather: 8 addresses x 3 channels = 24 independent LDGs ----
    const float* base = img + (size_t)b * 3 * PLANE;

    const float* p00 = base + r0[0] * IN_SZ + c0;
    const float* p01 = base + r0[0] * IN_SZ + c1;
    const float* p10 = base + r1[0] * IN_SZ + c0;
    const float* p11 = base + r1[0] * IN_SZ + c1;
    const float* q00 = base + r0[1] * IN_SZ + c0;
    const float* q01 = base + r0[1] * IN_SZ + c1;
    const float* q10 = base + r1[1] * IN_SZ + c0;
    const float* q11 = base + r1[1] * IN_SZ + c1;

    float v[3][8];
    #pragma unroll
    for (int ch = 0; ch < 3; ch++) {
        const int o = ch * PLANE;
        v[ch][0] = __ldg(p00 + o);
        v[ch][1] = __ldg(p01 + o);
        v[ch][2] = __ldg(p10 + o);
        v[ch][3] = __ldg(p11 + o);
        v[ch][4] = __ldg(q00 + o);
        v[ch][5] = __ldg(q01 + o);
        v[ch][6] = __ldg(q10 + o);
        v[ch][7] = __ldg(q11 + o);
    }

    float* obase = out + (size_t)b * 3 * OUT_SZ * OUT_SZ + jr * OUT_SZ + jc;

    #pragma unroll
    for (int ch = 0; ch < 3; ch++) {
        const float t0 = fmaf(a1, v[ch][1], a0 * v[ch][0]);
        const float u0 = fmaf(a1, v[ch][3], a0 * v[ch][2]);
        const float t1 = fmaf(a1, v[ch][5], a0 * v[ch][4]);
        const float u1 = fmaf(a1, v[ch][7], a0 * v[ch][6]);
        float* op = obase + (size_t)ch * OUT_SZ * OUT_SZ;
        op[0]      = fmaf(b1[0], u0, b0[0] * t0);
        op[OUT_SZ] = fmaf(b1[1], u1, b0[1] * t1);
    }
}

// ---------------------------------------------------------------------------
extern "C" void kernel_launch(void* const* d_in, const int* in_sizes, int n_in,
                              void* d_out, int out_size)
{
    const float* images = (const float*)d_in[0];
    const float* locs   = (const float*)d_in[1];
    if (n_in >= 2 && in_sizes[0] == BATCH * 3) {
        locs   = (const float*)d_in[0];
        images = (const float*)d_in[1];
    }
    float* out = (float*)d_out;

    dim3 block(32, 8, 1);                 // 256 threads
    dim3 grid(7, 14, BATCH);              // (7, 14, 64)
    racnn_kernel<<<grid, block>>>(images, locs, out);
}

// round 12
// speedup vs baseline: 1.2279x; 1.1606x over previous
#include <cuda_runtime.h>

#define IN_SZ   448
#define OUT_SZ  224
#define BATCH   64
#define PLANE   (IN_SZ * IN_SZ)
#define NTILES  (7 * 14 * BATCH)      // 6272
#define GRIDSZ  896                   // 6272 / 7 exactly; ~148*6 residency

// Per-(image, output index) coefficients (mask folded in)
__device__ float2 g_a[BATCH * OUT_SZ];   // col (a0, a1)
__device__ int2   g_c[BATCH * OUT_SZ];   // col (c0, c1)
__device__ float2 g_b[BATCH * OUT_SZ];   // row (b0, b1)
__device__ int2   g_r[BATCH * OUT_SZ];   // row (r0, r1)

__device__ __forceinline__ float sig10(float z) {
    return 1.0f / (1.0f + __expf(-10.0f * z));
}

// ---------------------------------------------------------------------------
// Prologue: coefficients. grid=64, block=224. Tiny.
// ---------------------------------------------------------------------------
__global__ void racnn_coef_kernel(const float* __restrict__ locs) {
    const int b = blockIdx.x;
    const int j = threadIdx.x;            // 0..223

    float tx = locs[b * 3 + 0];
    float ty = locs[b * 3 + 1];
    float tl = locs[b * 3 + 2];

    tl = fmaxf(tl, 448.0f / 3.0f);
    tx = fminf(fmaxf(tx, tl), 448.0f - tl);
    ty = fminf(fmaxf(ty, tl), 448.0f - tl);

    const float w_off = fmaxf(floorf(tx - tl), 0.0f);
    const float h_off = fmaxf(floorf(ty - tl), 0.0f);
    const float w_end = fminf(floorf(tx + tl), 448.0f);
    const float h_end = fminf(floorf(ty + tl), 448.0f);

    const float fj = (float)j;

    // row side (w axis)
    {
        const float step = (w_end - w_off - 1.0f) * (1.0f / 223.0f);
        const float src  = w_off + fj * step;
        const float r0f  = fminf(fmaxf(floorf(src), 0.0f), 447.0f);
        const float wr   = src - r0f;
        const int   r0   = (int)r0f;
        const int   r1   = min(r0 + 1, IN_SZ - 1);
        const float mr0  = sig10(r0f - w_off) - sig10(r0f - w_end);
        const float mr1  = sig10((float)r1 - w_off) - sig10((float)r1 - w_end);
        g_b[b * OUT_SZ + j] = make_float2((1.0f - wr) * mr0, wr * mr1);
        g_r[b * OUT_SZ + j] = make_int2(r0, r1);
    }

    // column side (h axis)
    {
        const float step = (h_end - h_off - 1.0f) * (1.0f / 223.0f);
        const float src  = h_off + fj * step;
        const float c0f  = fminf(fmaxf(floorf(src), 0.0f), 447.0f);
        const float wc   = src - c0f;
        const int   c0   = (int)c0f;
        const int   c1   = min(c0 + 1, IN_SZ - 1);
        const float mc0  = sig10(c0f - h_off) - sig10(c0f - h_end);
        const float mc1  = sig10((float)c1 - h_off) - sig10((float)c1 - h_end);
        g_a[b * OUT_SZ + j] = make_float2((1.0f - wc) * mc0, wc * mc1);
        g_c[b * OUT_SZ + j] = make_int2(c0, c1);
    }
}

// ---------------------------------------------------------------------------
// Main gather, persistent-style: 896 blocks x 256 threads, 7 tiles per block.
// Tile = 32 cols x 16 rows x 3 channels of one image; thread = 1 col x 2 rows
// x 3 ch = 6 px, 24 independent gather LDGs. No barriers -> iterations overlap.
// ---------------------------------------------------------------------------
__global__ __launch_bounds__(256) void racnn_gather_kernel(
    const float* __restrict__ img, float* __restrict__ out)
{
    for (int t = blockIdx.x; t < NTILES; t += GRIDSZ) {
        const int tx  = t % 7;
        const int rem = t / 7;
        const int ty  = rem % 14;
        const int b   = rem / 14;

        const int jc = tx * 32 + threadIdx.x;          // 0..223
        const int jr = ty * 16 + threadIdx.y * 2;      // first of 2 rows

        const float2 a = __ldg(&g_a[b * OUT_SZ + jc]);
        const int2   c = __ldg(&g_c[b * OUT_SZ + jc]);

        const int2   r0 = __ldg(&g_r[b * OUT_SZ + jr]);        // warp-uniform
        const int2   r1 = __ldg(&g_r[b * OUT_SZ + jr + 1]);
        const float2 b0 = __ldg(&g_b[b * OUT_SZ + jr]);
        const float2 b1 = __ldg(&g_b[b * OUT_SZ + jr + 1]);

        const float* base = img + (size_t)b * 3 * PLANE;

        const float* p00 = base + r0.x * IN_SZ + c.x;
        const float* p01 = base + r0.x * IN_SZ + c.y;
        const float* p10 = base + r0.y * IN_SZ + c.x;
        const float* p11 = base + r0.y * IN_SZ + c.y;
        const float* q00 = base + r1.x * IN_SZ + c.x;
        const float* q01 = base + r1.x * IN_SZ + c.y;
        const float* q10 = base + r1.y * IN_SZ + c.x;
        const float* q11 = base + r1.y * IN_SZ + c.y;

        float v[3][8];
        #pragma unroll
        for (int ch = 0; ch < 3; ch++) {
            const int o = ch * PLANE;
            v[ch][0] = __ldg(p00 + o);
            v[ch][1] = __ldg(p01 + o);
            v[ch][2] = __ldg(p10 + o);
            v[ch][3] = __ldg(p11 + o);
            v[ch][4] = __ldg(q00 + o);
            v[ch][5] = __ldg(q01 + o);
            v[ch][6] = __ldg(q10 + o);
            v[ch][7] = __ldg(q11 + o);
        }

        float* obase = out + (size_t)b * 3 * OUT_SZ * OUT_SZ + jr * OUT_SZ + jc;

        #pragma unroll
        for (int ch = 0; ch < 3; ch++) {
            const float t0 = fmaf(a.y, v[ch][1], a.x * v[ch][0]);
            const float u0 = fmaf(a.y, v[ch][3], a.x * v[ch][2]);
            const float t1 = fmaf(a.y, v[ch][5], a.x * v[ch][4]);
            const float u1 = fmaf(a.y, v[ch][7], a.x * v[ch][6]);
            float* op = obase + (size_t)ch * OUT_SZ * OUT_SZ;
            __stcs(op,          fmaf(b0.y, u0, b0.x * t0));   // streaming store
            __stcs(op + OUT_SZ, fmaf(b1.y, u1, b1.x * t1));
        }
    }
}

// ---------------------------------------------------------------------------
extern "C" void kernel_launch(void* const* d_in, const int* in_sizes, int n_in,
                              void* d_out, int out_size)
{
    const float* images = (const float*)d_in[0];
    const float* locs   = (const float*)d_in[1];
    if (n_in >= 2 && in_sizes[0] == BATCH * 3) {
        locs   = (const float*)d_in[0];
        images = (const float*)d_in[1];
    }
    float* out = (float*)d_out;

    racnn_coef_kernel<<<BATCH, OUT_SZ>>>(locs);

    dim3 block(32, 8, 1);                 // 256 threads
    racnn_gather_kernel<<<GRIDSZ, block>>>(images, out);
}